// round 14
// baseline (speedup 1.0000x reference)
#include <cuda_runtime.h>
#include <cuda_bf16.h>
#include <cstdint>
#include <cstddef>
#include <cstdio>

#define S_LEN 8192
#define EDIM  300           // embedding dim (E) — NOT 768!
#define HID   768
#define HX4   3072
#define NVOC  100000
#define NDIR  2
#define CTAS_PER_DIR 64
#define M_PER_CTA    12
#define REC_THREADS  512

// ---------------- scratch (static device memory; no runtime alloc) ---------
__device__ __align__(256) float g_gates[NDIR][S_LEN][HX4];
__device__ __align__(256) float g_h[2][NDIR][HID];
__device__ __align__(256) int   g_flags[NDIR][CTAS_PER_DIR];

__device__ __forceinline__ float sigmf(float x) { return 1.0f / (1.0f + expf(-x)); }
__device__ __forceinline__ size_t cmin(size_t a, size_t b) { return a < b ? a : b; }

// ============================================================================
__global__ void init_kernel() {
    int i = blockIdx.x * blockDim.x + threadIdx.x;
    float* hp = &g_h[0][0][0];
    int*   fp = &g_flags[0][0];
    if (i < 2 * NDIR * HID) hp[i] = 0.0f;
    if (i < NDIR * CTAS_PER_DIR) fp[i] = 0;
}

// ============================================================================
// Kernel A: gates[dir][t][r] = sum_{k<300} emb[idx[t]][k]*W_ih[r][k] + bias[r]
// 128x128 tile, K=300 in 15 chunks of 20. Tokens int32 or int64 (probed).
// ============================================================================
#define GBM 128
#define GBN 128
#define GBK 20
#define NKT (EDIM / GBK)        // 15
#define GEMM_THREADS 256
#define NF4 (GBM * (GBK / 4))   // 640 float4 loads per tile side

__global__ __launch_bounds__(GEMM_THREADS) void gates_gemm_kernel(
    const int*   __restrict__ idx,  int idx_cl,
    const float* __restrict__ emb,  int emb_cl,
    const float* __restrict__ Wf,   const float* __restrict__ Wb, int w_cl,
    const float* __restrict__ bihf, const float* __restrict__ bhhf,
    const float* __restrict__ bihb, const float* __restrict__ bhhb, int b_cl)
{
    __shared__ __align__(16) float As[GBK][GBM];
    __shared__ __align__(16) float Bs[GBK][GBN];
    __shared__ int sidx[GBM];

    const int tid = threadIdx.x;
    const int bm  = blockIdx.x;                 // time tile
    const int bn  = blockIdx.y;                 // row tile over 2*3072
    const int dir = (bn >= (HX4 / GBN)) ? 1 : 0;
    const int rbase = bn * GBN - dir * HX4;
    const float* __restrict__ W  = dir ? Wb   : Wf;
    const float* __restrict__ bi = dir ? bihb : bihf;
    const float* __restrict__ bh = dir ? bhhb : bhhf;

    if (tid < GBM) {
        // token dtype probe: int64 little-endian < 2^31 -> odd words all 0
        int probe = 0;
        if (idx_cl >= 7) probe = idx[1] | idx[3] | idx[5] | idx[7];
        bool i64 = (idx_cl >= 7) && (probe == 0);

        int ii = bm * GBM + tid;                // 0..8191
        int v  = i64 ? idx[2 * ii]
                     : idx[(ii > idx_cl) ? idx_cl : ii];
        v = (v < 0) ? 0 : ((v >= NVOC) ? NVOC - 1 : v);
        sidx[tid] = v;
    }
    __syncthreads();

    const int tx = tid & 15;      // n micro
    const int ty = tid >> 4;      // m micro

    float bsum[8];
    #pragma unroll
    for (int j = 0; j < 8; j++) {
        int r = rbase + tx * 8 + j;
        if (r > b_cl) r = b_cl;
        bsum[j] = bi[r] + bh[r];
    }

    float acc[8][8];
    #pragma unroll
    for (int i = 0; i < 8; i++)
        #pragma unroll
        for (int j = 0; j < 8; j++) acc[i][j] = 0.0f;

    for (int kt = 0; kt < NKT; kt++) {
        const int kb = kt * GBK;
        // A tile: 128 gathered emb rows x 20 k (5 float4 per row)
        for (int lin = tid; lin < NF4; lin += GEMM_THREADS) {
            int m = lin / 5;
            int q = lin % 5;
            size_t off = cmin((size_t)sidx[m] * EDIM + kb + q * 4,
                              (size_t)emb_cl);
            float4 v = *reinterpret_cast<const float4*>(&emb[off]);
            As[q * 4 + 0][m] = v.x; As[q * 4 + 1][m] = v.y;
            As[q * 4 + 2][m] = v.z; As[q * 4 + 3][m] = v.w;
        }
        // B tile: 128 weight rows x 20 k
        for (int lin = tid; lin < NF4; lin += GEMM_THREADS) {
            int nrow = lin / 5;
            int q    = lin % 5;
            size_t off = cmin((size_t)(rbase + nrow) * EDIM + kb + q * 4,
                              (size_t)w_cl);
            float4 v = *reinterpret_cast<const float4*>(&W[off]);
            Bs[q * 4 + 0][nrow] = v.x; Bs[q * 4 + 1][nrow] = v.y;
            Bs[q * 4 + 2][nrow] = v.z; Bs[q * 4 + 3][nrow] = v.w;
        }
        __syncthreads();

        #pragma unroll
        for (int k = 0; k < GBK; k++) {
            float4 a0 = *reinterpret_cast<const float4*>(&As[k][ty * 8]);
            float4 a1 = *reinterpret_cast<const float4*>(&As[k][ty * 8 + 4]);
            float4 b0 = *reinterpret_cast<const float4*>(&Bs[k][tx * 8]);
            float4 b1 = *reinterpret_cast<const float4*>(&Bs[k][tx * 8 + 4]);
            float av[8] = {a0.x, a0.y, a0.z, a0.w, a1.x, a1.y, a1.z, a1.w};
            float bv[8] = {b0.x, b0.y, b0.z, b0.w, b1.x, b1.y, b1.z, b1.w};
            #pragma unroll
            for (int i = 0; i < 8; i++)
                #pragma unroll
                for (int j = 0; j < 8; j++)
                    acc[i][j] = fmaf(av[i], bv[j], acc[i][j]);
        }
        __syncthreads();
    }

    #pragma unroll
    for (int i = 0; i < 8; i++) {
        int t = bm * GBM + ty * 8 + i;
        float* outp = &g_gates[dir][t][rbase + tx * 8];
        float4 o0 = make_float4(acc[i][0] + bsum[0], acc[i][1] + bsum[1],
                                acc[i][2] + bsum[2], acc[i][3] + bsum[3]);
        float4 o1 = make_float4(acc[i][4] + bsum[4], acc[i][5] + bsum[5],
                                acc[i][6] + bsum[6], acc[i][7] + bsum[7]);
        *reinterpret_cast<float4*>(&outp[0]) = o0;
        *reinterpret_cast<float4*>(&outp[4]) = o1;
    }
}

// ============================================================================
// Kernel B: persistent recurrence. W_hh (3072x768) register-resident.
// 128 CTAs (64/dir) x 512 thr; flag barrier; double-buffered h via L2.
// ============================================================================
__global__ __launch_bounds__(REC_THREADS, 1) void lstm_rec_kernel(
    const float* __restrict__ Whhf, const float* __restrict__ Whhb, int whh_cl)
{
    __shared__ __align__(16) float sh[HID];
    __shared__ __align__(16) float sg[48];

    const int tid  = threadIdx.x;
    const int b    = blockIdx.x;
    const int dir  = b >> 6;
    const int lb   = b & 63;
    const int m0   = lb * M_PER_CTA;

    const int w    = tid >> 5;
    const int l    = tid & 31;
    const int gate = w >> 2;
    const int rsub = 3 * (w & 3);

    const float* __restrict__ Whh = dir ? Whhb : Whhf;

    float wr[3][24];
    #pragma unroll
    for (int j = 0; j < 3; j++) {
        int grow = gate * HID + m0 + rsub + j;
        #pragma unroll
        for (int c = 0; c < 6; c++) {
            size_t off = cmin((size_t)grow * HID + c * 128 + 4 * l,
                              (size_t)whh_cl);
            float4 v = *reinterpret_cast<const float4*>(&Whh[off]);
            wr[j][4 * c + 0] = v.x; wr[j][4 * c + 1] = v.y;
            wr[j][4 * c + 2] = v.z; wr[j][4 * c + 3] = v.w;
        }
    }

    float creg = 0.0f;
    volatile int* flg = (volatile int*)g_flags[dir];
    const float* Gd = &g_gates[dir][0][0];

    for (int t = 0; t < S_LEN; t++) {
        float pg0 = 0.f, pg1 = 0.f, pg2 = 0.f, pg3 = 0.f;
        if (tid < M_PER_CTA) {
            const float* G = Gd + (size_t)t * HX4;
            int m = m0 + tid;
            pg0 = __ldcg(&G[m]);
            pg1 = __ldcg(&G[768 + m]);
            pg2 = __ldcg(&G[1536 + m]);
            pg3 = __ldcg(&G[2304 + m]);
        }

        int pending;
        do {
            int p = 0;
            if (tid < CTAS_PER_DIR) p = (flg[tid] < t) ? 1 : 0;
            pending = __syncthreads_or(p);
        } while (pending);
        __threadfence();   // acquire

        const int par = t & 1;
        if (tid < HID / 4) {
            float4 hv = __ldcg(reinterpret_cast<const float4*>(
                                   &g_h[par][dir][tid * 4]));
            *reinterpret_cast<float4*>(&sh[tid * 4]) = hv;
        }
        __syncthreads();

        float a0 = 0.f, a1 = 0.f, a2 = 0.f;
        #pragma unroll
        for (int c = 0; c < 6; c++) {
            float4 hv = *reinterpret_cast<const float4*>(&sh[c * 128 + 4 * l]);
            a0 = fmaf(wr[0][4*c+0], hv.x, a0); a0 = fmaf(wr[0][4*c+1], hv.y, a0);
            a0 = fmaf(wr[0][4*c+2], hv.z, a0); a0 = fmaf(wr[0][4*c+3], hv.w, a0);
            a1 = fmaf(wr[1][4*c+0], hv.x, a1); a1 = fmaf(wr[1][4*c+1], hv.y, a1);
            a1 = fmaf(wr[1][4*c+2], hv.z, a1); a1 = fmaf(wr[1][4*c+3], hv.w, a1);
            a2 = fmaf(wr[2][4*c+0], hv.x, a2); a2 = fmaf(wr[2][4*c+1], hv.y, a2);
            a2 = fmaf(wr[2][4*c+2], hv.z, a2); a2 = fmaf(wr[2][4*c+3], hv.w, a2);
        }
        #pragma unroll
        for (int off = 16; off; off >>= 1) {
            a0 += __shfl_xor_sync(0xffffffffu, a0, off);
            a1 += __shfl_xor_sync(0xffffffffu, a1, off);
            a2 += __shfl_xor_sync(0xffffffffu, a2, off);
        }
        if (l == 0) {
            sg[gate * 12 + rsub + 0] = a0;
            sg[gate * 12 + rsub + 1] = a1;
            sg[gate * 12 + rsub + 2] = a2;
        }
        __syncthreads();

        if (tid < M_PER_CTA) {
            float gi = sg[tid]      + pg0;
            float gf = sg[12 + tid] + pg1;
            float gg = sg[24 + tid] + pg2;
            float go = sg[36 + tid] + pg3;
            float cn = sigmf(gf) * creg + sigmf(gi) * tanhf(gg);
            float hn = sigmf(go) * tanhf(cn);
            creg = cn;
            __stcg(&g_h[par ^ 1][dir][m0 + tid], hn);
        }
        __syncthreads();
        if (tid == 0) {
            __threadfence();   // release
            *((volatile int*)&g_flags[dir][lb]) = t + 1;
        }
    }
}

// ============================================================================
// Kernel C: out[j] = b_tag[j] + W_tag[j] . concat(hf, hb)   (20 x 1536)
// ============================================================================
__global__ void tag_kernel(const float* __restrict__ Wt, int wt_cl,
                           const float* __restrict__ bt, int bt_cl,
                           float* __restrict__ out, int out_cl)
{
    const int w = threadIdx.x >> 5;   // 0..19
    const int l = threadIdx.x & 31;
    const float* hf = g_h[0][0];      // S_LEN even -> final h in buffer 0
    const float* hb = g_h[0][1];
    float s = 0.0f;
    for (int i = 0; i < 48; i++) {
        int k = i * 32 + l;
        float x = (k < HID) ? hf[k] : hb[k - HID];
        int wk = w * (2 * HID) + k; if (wk > wt_cl) wk = wt_cl;
        s = fmaf(Wt[wk], x, s);
    }
    #pragma unroll
    for (int off = 16; off; off >>= 1) s += __shfl_xor_sync(0xffffffffu, s, off);
    if (l == 0 && w <= out_cl) {
        int bw = (w > bt_cl) ? bt_cl : w;
        out[w] = s + bt[bw];
    }
}

// ============================================================================
extern "C" void kernel_launch(void* const* d_in, const int* in_sizes, int n_in,
                              void* d_out, int out_size)
{
    // VERIFIED (round-13 forensics): signature order, sizes in ELEMENTS:
    //  0 inpu (int64, 8192 tokens)   1 emb (100000x300)
    //  2 W_ih_f (3072x300)           3 W_hh_f (3072x768)
    //  4 b_ih_f (3072)               5 b_hh_f (3072)
    //  6 W_ih_b (3072x300)           7 W_hh_b (3072x768)
    //  8 b_ih_b (3072)               9 b_hh_b (3072)
    // 10 W_tag (20x1536)            11 b_tag (20)
    const int*   inpu = (const int*)  d_in[0];
    const float* emb  = (const float*)d_in[1];
    const float* Wihf = (const float*)d_in[2];
    const float* Whhf = (const float*)d_in[3];
    const float* bihf = (const float*)d_in[4];
    const float* bhhf = (const float*)d_in[5];
    const float* Wihb = (const float*)d_in[6];
    const float* Whhb = (const float*)d_in[7];
    const float* bihb = (const float*)d_in[8];
    const float* bhhb = (const float*)d_in[9];
    const float* Wtag = (const float*)d_in[10];
    const float* btag = (const float*)d_in[11];
    float* out = (float*)d_out;

    auto c4 = [&](int i) -> int {          // max float4-safe element offset
        long long s = in_sizes[i];
        long long c = (s / 4) * 4 - 4;
        if (c < 0) c = 0;
        return (int)c;
    };
    auto c1 = [&](int i) -> int {
        long long s = in_sizes[i];
        return (int)((s > 0) ? s - 1 : 0);
    };

    init_kernel<<<13, 256>>>();

    dim3 ggrid(S_LEN / GBM, (NDIR * HX4) / GBN);   // (64, 48)
    gates_gemm_kernel<<<ggrid, GEMM_THREADS>>>(
        inpu, c1(0), emb, c4(1), Wihf, Wihb, c4(2),
        bihf, bhhf, bihb, bhhb, c1(4));
    lstm_rec_kernel<<<NDIR * CTAS_PER_DIR, REC_THREADS>>>(Whhf, Whhb, c4(3));
    tag_kernel<<<1, 640>>>(Wtag, c1(10), btag, c1(11), out,
                           (out_size > 0) ? out_size - 1 : 0);
}

// round 15
// speedup vs baseline: 2.0571x; 2.0571x over previous
#include <cuda_runtime.h>
#include <cuda_bf16.h>
#include <cstdint>
#include <cstddef>

#define S_LEN 8192
#define EDIM  300
#define HID   768
#define HX4   3072
#define NVOC  100000
#define NDIR  2
#define CTAS_PER_DIR 64
#define M_PER_CTA    12
#define REC_THREADS  512

// ---------------- scratch (static device memory; no runtime alloc) ---------
__device__ __align__(256) float    g_gates[NDIR][S_LEN][HX4];
__device__ __align__(256) float    g_h[2][NDIR][HID];
__device__ __align__(128) unsigned g_ctr[NDIR * 32];   // one line per dir

__device__ __forceinline__ float sigmf(float x) { return 1.0f / (1.0f + expf(-x)); }
__device__ __forceinline__ size_t cmin(size_t a, size_t b) { return a < b ? a : b; }

__device__ __forceinline__ unsigned ld_acq(const unsigned* p) {
    unsigned v;
    asm volatile("ld.acquire.gpu.u32 %0, [%1];" : "=r"(v) : "l"(p) : "memory");
    return v;
}
__device__ __forceinline__ void red_rel_add1(unsigned* p) {
    asm volatile("red.release.gpu.add.u32 [%0], 1;" :: "l"(p) : "memory");
}

// ============================================================================
// Kernel A: gates = gather(emb, idx) @ W_ih^T + (b_ih + b_hh)
// K=300 in 15 chunks of 20. Block (0,0) also re-inits h buffers + counters.
// ============================================================================
#define GBM 128
#define GBN 128
#define GBK 20
#define NKT (EDIM / GBK)
#define GEMM_THREADS 256
#define NF4 (GBM * (GBK / 4))

__global__ __launch_bounds__(GEMM_THREADS) void gates_gemm_kernel(
    const int*   __restrict__ idx,  int idx_cl,
    const float* __restrict__ emb,  int emb_cl,
    const float* __restrict__ Wf,   const float* __restrict__ Wb, int w_cl,
    const float* __restrict__ bihf, const float* __restrict__ bhhf,
    const float* __restrict__ bihb, const float* __restrict__ bhhb, int b_cl)
{
    __shared__ __align__(16) float As[GBK][GBM];
    __shared__ __align__(16) float Bs[GBK][GBN];
    __shared__ int sidx[GBM];

    const int tid = threadIdx.x;
    const int bm  = blockIdx.x;
    const int bn  = blockIdx.y;

    // per-replay re-init (this block only; rec kernel runs strictly after)
    if (bm == 0 && bn == 0) {
        float* hp = &g_h[0][0][0];
        for (int i = tid; i < 2 * NDIR * HID; i += GEMM_THREADS) hp[i] = 0.0f;
        if (tid < NDIR * 32) g_ctr[tid] = 0u;
    }

    const int dir = (bn >= (HX4 / GBN)) ? 1 : 0;
    const int rbase = bn * GBN - dir * HX4;
    const float* __restrict__ W  = dir ? Wb   : Wf;
    const float* __restrict__ bi = dir ? bihb : bihf;
    const float* __restrict__ bh = dir ? bhhb : bhhf;

    if (tid < GBM) {
        // token dtype probe: int64 little-endian < 2^31 -> odd words all 0
        int probe = 0;
        if (idx_cl >= 7) probe = idx[1] | idx[3] | idx[5] | idx[7];
        bool i64 = (idx_cl >= 7) && (probe == 0);
        int ii = bm * GBM + tid;
        int v  = i64 ? idx[2 * ii] : idx[(ii > idx_cl) ? idx_cl : ii];
        v = (v < 0) ? 0 : ((v >= NVOC) ? NVOC - 1 : v);
        sidx[tid] = v;
    }
    __syncthreads();

    const int tx = tid & 15;
    const int ty = tid >> 4;

    float bsum[8];
    #pragma unroll
    for (int j = 0; j < 8; j++) {
        int r = rbase + tx * 8 + j;
        if (r > b_cl) r = b_cl;
        bsum[j] = bi[r] + bh[r];
    }

    float acc[8][8];
    #pragma unroll
    for (int i = 0; i < 8; i++)
        #pragma unroll
        for (int j = 0; j < 8; j++) acc[i][j] = 0.0f;

    for (int kt = 0; kt < NKT; kt++) {
        const int kb = kt * GBK;
        for (int lin = tid; lin < NF4; lin += GEMM_THREADS) {
            int m = lin / 5, q = lin % 5;
            size_t off = cmin((size_t)sidx[m] * EDIM + kb + q * 4, (size_t)emb_cl);
            float4 v = *reinterpret_cast<const float4*>(&emb[off]);
            As[q * 4 + 0][m] = v.x; As[q * 4 + 1][m] = v.y;
            As[q * 4 + 2][m] = v.z; As[q * 4 + 3][m] = v.w;
        }
        for (int lin = tid; lin < NF4; lin += GEMM_THREADS) {
            int nrow = lin / 5, q = lin % 5;
            size_t off = cmin((size_t)(rbase + nrow) * EDIM + kb + q * 4,
                              (size_t)w_cl);
            float4 v = *reinterpret_cast<const float4*>(&W[off]);
            Bs[q * 4 + 0][nrow] = v.x; Bs[q * 4 + 1][nrow] = v.y;
            Bs[q * 4 + 2][nrow] = v.z; Bs[q * 4 + 3][nrow] = v.w;
        }
        __syncthreads();

        #pragma unroll
        for (int k = 0; k < GBK; k++) {
            float4 a0 = *reinterpret_cast<const float4*>(&As[k][ty * 8]);
            float4 a1 = *reinterpret_cast<const float4*>(&As[k][ty * 8 + 4]);
            float4 b0 = *reinterpret_cast<const float4*>(&Bs[k][tx * 8]);
            float4 b1 = *reinterpret_cast<const float4*>(&Bs[k][tx * 8 + 4]);
            float av[8] = {a0.x, a0.y, a0.z, a0.w, a1.x, a1.y, a1.z, a1.w};
            float bv[8] = {b0.x, b0.y, b0.z, b0.w, b1.x, b1.y, b1.z, b1.w};
            #pragma unroll
            for (int i = 0; i < 8; i++)
                #pragma unroll
                for (int j = 0; j < 8; j++)
                    acc[i][j] = fmaf(av[i], bv[j], acc[i][j]);
        }
        __syncthreads();
    }

    #pragma unroll
    for (int i = 0; i < 8; i++) {
        int t = bm * GBM + ty * 8 + i;
        float* outp = &g_gates[dir][t][rbase + tx * 8];
        float4 o0 = make_float4(acc[i][0] + bsum[0], acc[i][1] + bsum[1],
                                acc[i][2] + bsum[2], acc[i][3] + bsum[3]);
        float4 o1 = make_float4(acc[i][4] + bsum[4], acc[i][5] + bsum[5],
                                acc[i][6] + bsum[6], acc[i][7] + bsum[7]);
        *reinterpret_cast<float4*>(&outp[0]) = o0;
        *reinterpret_cast<float4*>(&outp[4]) = o1;
    }
}

// ============================================================================
// Kernel B: persistent recurrence + final hidden2tag (block 0 tail).
// Sync: per-dir monotonic counter, red.release by the h-storing thread,
// ld.acquire polls by the staging warps. NO threadfence, NO barrier spin.
// ============================================================================
__global__ __launch_bounds__(REC_THREADS, 1) void lstm_rec_kernel(
    const float* __restrict__ Whhf, const float* __restrict__ Whhb, int whh_cl,
    const float* __restrict__ Wt, int wt_cl,
    const float* __restrict__ bt, int bt_cl,
    float* __restrict__ out, int out_cl)
{
    __shared__ __align__(16) float sh[HID];
    __shared__ __align__(16) float sg[48];
    __shared__ __align__(16) float hout[M_PER_CTA];

    const int tid  = threadIdx.x;
    const int b    = blockIdx.x;
    const int dir  = b >> 6;
    const int lb   = b & 63;
    const int m0   = lb * M_PER_CTA;

    const int w    = tid >> 5;
    const int l    = tid & 31;
    const int gate = w >> 2;
    const int rsub = 3 * (w & 3);

    const float* __restrict__ Whh = dir ? Whhb : Whhf;
    unsigned* ctr = &g_ctr[dir * 32];

    // register-resident W_hh slice: 3 rows x 24 cols per thread
    float wr[3][24];
    #pragma unroll
    for (int j = 0; j < 3; j++) {
        int grow = gate * HID + m0 + rsub + j;
        #pragma unroll
        for (int c = 0; c < 6; c++) {
            size_t off = cmin((size_t)grow * HID + c * 128 + 4 * l,
                              (size_t)whh_cl);
            float4 v = *reinterpret_cast<const float4*>(&Whh[off]);
            wr[j][4 * c + 0] = v.x; wr[j][4 * c + 1] = v.y;
            wr[j][4 * c + 2] = v.z; wr[j][4 * c + 3] = v.w;
        }
    }

    float creg = 0.0f;
    const float* Gd = &g_gates[dir][0][0];

    for (int t = 0; t < S_LEN; t++) {
        // prefetch this step's input-projection gates (independent of h)
        float pg0 = 0.f, pg1 = 0.f, pg2 = 0.f, pg3 = 0.f;
        if (tid < M_PER_CTA) {
            const float* G = Gd + (size_t)t * HX4;
            int m = m0 + tid;
            pg0 = __ldcg(&G[m]);
            pg1 = __ldcg(&G[768 + m]);
            pg2 = __ldcg(&G[1536 + m]);
            pg3 = __ldcg(&G[2304 + m]);
        }

        // wait: all CTAs of this dir published step t-1 (ctr >= 64*t).
        // Only the h-staging warps (tid<192) need the acquire ordering.
        const unsigned target = 64u * (unsigned)t;
        if (tid < HID / 4) {
            while (ld_acq(ctr) < target) { }
            float4 hv = __ldcg(reinterpret_cast<const float4*>(
                                   &g_h[t & 1][dir][tid * 4]));
            *reinterpret_cast<float4*>(&sh[tid * 4]) = hv;
        }
        __syncthreads();

        // matvec: 3 rows x 24 cols per thread
        float a0 = 0.f, a1 = 0.f, a2 = 0.f;
        #pragma unroll
        for (int c = 0; c < 6; c++) {
            float4 hv = *reinterpret_cast<const float4*>(&sh[c * 128 + 4 * l]);
            a0 = fmaf(wr[0][4*c+0], hv.x, a0); a0 = fmaf(wr[0][4*c+1], hv.y, a0);
            a0 = fmaf(wr[0][4*c+2], hv.z, a0); a0 = fmaf(wr[0][4*c+3], hv.w, a0);
            a1 = fmaf(wr[1][4*c+0], hv.x, a1); a1 = fmaf(wr[1][4*c+1], hv.y, a1);
            a1 = fmaf(wr[1][4*c+2], hv.z, a1); a1 = fmaf(wr[1][4*c+3], hv.w, a1);
            a2 = fmaf(wr[2][4*c+0], hv.x, a2); a2 = fmaf(wr[2][4*c+1], hv.y, a2);
            a2 = fmaf(wr[2][4*c+2], hv.z, a2); a2 = fmaf(wr[2][4*c+3], hv.w, a2);
        }
        #pragma unroll
        for (int off = 16; off; off >>= 1) {
            a0 += __shfl_xor_sync(0xffffffffu, a0, off);
            a1 += __shfl_xor_sync(0xffffffffu, a1, off);
            a2 += __shfl_xor_sync(0xffffffffu, a2, off);
        }
        if (l == 0) {
            sg[gate * 12 + rsub + 0] = a0;
            sg[gate * 12 + rsub + 1] = a1;
            sg[gate * 12 + rsub + 2] = a2;
        }
        __syncthreads();

        // gate fusion (c stays in registers of threads 0..11)
        if (tid < M_PER_CTA) {
            float gi = sg[tid]      + pg0;
            float gf = sg[12 + tid] + pg1;
            float gg = sg[24 + tid] + pg2;
            float go = sg[36 + tid] + pg3;
            float cn = sigmf(gf) * creg + sigmf(gi) * tanhf(gg);
            float hn = sigmf(go) * tanhf(cn);
            creg = cn;
            hout[tid] = hn;
        }
        __syncthreads();

        // single-thread publish: h stores then release-increment (same thread
        // => all its prior stores are ordered before the increment).
        if (tid == 0) {
            float4* dst = reinterpret_cast<float4*>(&g_h[(t & 1) ^ 1][dir][m0]);
            const float4* src = reinterpret_cast<const float4*>(hout);
            __stcg(&dst[0], src[0]);
            __stcg(&dst[1], src[1]);
            __stcg(&dst[2], src[2]);
            red_rel_add1(ctr);
        }
        // no further syncthreads needed: next iteration's __syncthreads after
        // staging orders everything inside the CTA.
    }

    // -------- tail: block 0 computes hidden2tag once both dirs finish ------
    if (b == 0) {
        const unsigned done = 64u * (unsigned)S_LEN;
        while (ld_acq(&g_ctr[0]) < done) { }
        while (ld_acq(&g_ctr[32]) < done) { }
        // final h lives in buffer 0 (S_LEN even)
        const float* hf = g_h[0][0];
        const float* hb = g_h[0][1];
        for (int o = w; o < 20; o += 16) {
            float s = 0.0f;
            for (int i = 0; i < 48; i++) {
                int k = i * 32 + l;
                float x = (k < HID) ? __ldcg(&hf[k]) : __ldcg(&hb[k - HID]);
                int wk = o * (2 * HID) + k; if (wk > wt_cl) wk = wt_cl;
                s = fmaf(Wt[wk], x, s);
            }
            #pragma unroll
            for (int off = 16; off; off >>= 1)
                s += __shfl_xor_sync(0xffffffffu, s, off);
            if (l == 0 && o <= out_cl) {
                int bw = (o > bt_cl) ? bt_cl : o;
                out[o] = s + bt[bw];
            }
        }
    }
}

// ============================================================================
extern "C" void kernel_launch(void* const* d_in, const int* in_sizes, int n_in,
                              void* d_out, int out_size)
{
    // VERIFIED mapping (round-13 forensics): signature order, element counts:
    //  0 inpu(int64 x8192) 1 emb(100000x300) 2 W_ih_f(3072x300)
    //  3 W_hh_f(3072x768)  4 b_ih_f 5 b_hh_f 6 W_ih_b(3072x300)
    //  7 W_hh_b(3072x768)  8 b_ih_b 9 b_hh_b 10 W_tag(20x1536) 11 b_tag(20)
    const int*   inpu = (const int*)  d_in[0];
    const float* emb  = (const float*)d_in[1];
    const float* Wihf = (const float*)d_in[2];
    const float* Whhf = (const float*)d_in[3];
    const float* bihf = (const float*)d_in[4];
    const float* bhhf = (const float*)d_in[5];
    const float* Wihb = (const float*)d_in[6];
    const float* Whhb = (const float*)d_in[7];
    const float* bihb = (const float*)d_in[8];
    const float* bhhb = (const float*)d_in[9];
    const float* Wtag = (const float*)d_in[10];
    const float* btag = (const float*)d_in[11];
    float* out = (float*)d_out;

    auto c4 = [&](int i) -> int {
        long long s = in_sizes[i];
        long long c = (s / 4) * 4 - 4;
        if (c < 0) c = 0;
        return (int)c;
    };
    auto c1 = [&](int i) -> int {
        long long s = in_sizes[i];
        return (int)((s > 0) ? s - 1 : 0);
    };

    dim3 ggrid(S_LEN / GBM, (NDIR * HX4) / GBN);   // (64, 48)
    gates_gemm_kernel<<<ggrid, GEMM_THREADS>>>(
        inpu, c1(0), emb, c4(1), Wihf, Wihb, c4(2),
        bihf, bhhf, bihb, bhhb, c1(4));
    lstm_rec_kernel<<<NDIR * CTAS_PER_DIR, REC_THREADS>>>(
        Whhf, Whhb, c4(3), Wtag, c1(10), btag, c1(11), out,
        (out_size > 0) ? out_size - 1 : 0);
}

// round 16
// speedup vs baseline: 2.2846x; 1.1106x over previous
#include <cuda_runtime.h>
#include <cuda_bf16.h>
#include <cstdint>
#include <cstddef>

#define S_LEN 8192
#define EDIM  300
#define HID   768
#define HX4   3072
#define NVOC  100000
#define NDIR  2
#define CTAS_PER_DIR 64
#define M_PER_CTA    12
#define REC_THREADS  512

// ---------------- scratch (static device memory; no runtime alloc) ---------
__device__ __align__(256) float    g_gates[NDIR][S_LEN][HX4];
__device__ __align__(256) float    g_h[2][NDIR][HID];
__device__ __align__(256) unsigned g_ctr[NDIR * 128];   // 512B apart per dir

__device__ __forceinline__ float sigmf(float x) { return 1.0f / (1.0f + expf(-x)); }
__device__ __forceinline__ size_t cmin(size_t a, size_t b) { return a < b ? a : b; }

__device__ __forceinline__ unsigned ld_acq(const unsigned* p) {
    unsigned v;
    asm volatile("ld.acquire.gpu.u32 %0, [%1];" : "=r"(v) : "l"(p) : "memory");
    return v;
}
__device__ __forceinline__ void red_rel_add1(unsigned* p) {
    asm volatile("red.release.gpu.add.u32 [%0], 1;" :: "l"(p) : "memory");
}
__device__ __forceinline__ uint64_t pack2(float x, float y) {
    uint64_t r;
    asm("mov.b64 %0, {%1, %2};" : "=l"(r) : "f"(x), "f"(y));
    return r;
}
__device__ __forceinline__ void ffma2(uint64_t& d, uint64_t a, uint64_t b) {
    asm("fma.rn.f32x2 %0, %1, %2, %0;" : "+l"(d) : "l"(a), "l"(b));
}
__device__ __forceinline__ float2 unpack2(uint64_t v) {
    float2 r;
    asm("mov.b64 {%0, %1}, %2;" : "=f"(r.x), "=f"(r.y) : "l"(v));
    return r;
}

// ============================================================================
// Kernel A: gates = gather(emb, idx) @ W_ih^T + (b_ih + b_hh)
// K=300 in 15 chunks of 20. Block (0,0) re-inits h buffers + counters.
// ============================================================================
#define GBM 128
#define GBN 128
#define GBK 20
#define NKT (EDIM / GBK)
#define GEMM_THREADS 256
#define NF4 (GBM * (GBK / 4))

__global__ __launch_bounds__(GEMM_THREADS) void gates_gemm_kernel(
    const int*   __restrict__ idx,  int idx_cl,
    const float* __restrict__ emb,  int emb_cl,
    const float* __restrict__ Wf,   const float* __restrict__ Wb, int w_cl,
    const float* __restrict__ bihf, const float* __restrict__ bhhf,
    const float* __restrict__ bihb, const float* __restrict__ bhhb, int b_cl)
{
    __shared__ __align__(16) float As[GBK][GBM];
    __shared__ __align__(16) float Bs[GBK][GBN];
    __shared__ int sidx[GBM];

    const int tid = threadIdx.x;
    const int bm  = blockIdx.x;
    const int bn  = blockIdx.y;

    if (bm == 0 && bn == 0) {
        float* hp = &g_h[0][0][0];
        for (int i = tid; i < 2 * NDIR * HID; i += GEMM_THREADS) hp[i] = 0.0f;
        for (int i = tid; i < NDIR * 128; i += GEMM_THREADS) g_ctr[i] = 0u;
    }

    const int dir = (bn >= (HX4 / GBN)) ? 1 : 0;
    const int rbase = bn * GBN - dir * HX4;
    const float* __restrict__ W  = dir ? Wb   : Wf;
    const float* __restrict__ bi = dir ? bihb : bihf;
    const float* __restrict__ bh = dir ? bhhb : bhhf;

    if (tid < GBM) {
        int probe = 0;
        if (idx_cl >= 7) probe = idx[1] | idx[3] | idx[5] | idx[7];
        bool i64 = (idx_cl >= 7) && (probe == 0);
        int ii = bm * GBM + tid;
        int v  = i64 ? idx[2 * ii] : idx[(ii > idx_cl) ? idx_cl : ii];
        v = (v < 0) ? 0 : ((v >= NVOC) ? NVOC - 1 : v);
        sidx[tid] = v;
    }
    __syncthreads();

    const int tx = tid & 15;
    const int ty = tid >> 4;

    float bsum[8];
    #pragma unroll
    for (int j = 0; j < 8; j++) {
        int r = rbase + tx * 8 + j;
        if (r > b_cl) r = b_cl;
        bsum[j] = bi[r] + bh[r];
    }

    float acc[8][8];
    #pragma unroll
    for (int i = 0; i < 8; i++)
        #pragma unroll
        for (int j = 0; j < 8; j++) acc[i][j] = 0.0f;

    for (int kt = 0; kt < NKT; kt++) {
        const int kb = kt * GBK;
        for (int lin = tid; lin < NF4; lin += GEMM_THREADS) {
            int m = lin / 5, q = lin % 5;
            size_t off = cmin((size_t)sidx[m] * EDIM + kb + q * 4, (size_t)emb_cl);
            float4 v = *reinterpret_cast<const float4*>(&emb[off]);
            As[q * 4 + 0][m] = v.x; As[q * 4 + 1][m] = v.y;
            As[q * 4 + 2][m] = v.z; As[q * 4 + 3][m] = v.w;
        }
        for (int lin = tid; lin < NF4; lin += GEMM_THREADS) {
            int nrow = lin / 5, q = lin % 5;
            size_t off = cmin((size_t)(rbase + nrow) * EDIM + kb + q * 4,
                              (size_t)w_cl);
            float4 v = *reinterpret_cast<const float4*>(&W[off]);
            Bs[q * 4 + 0][nrow] = v.x; Bs[q * 4 + 1][nrow] = v.y;
            Bs[q * 4 + 2][nrow] = v.z; Bs[q * 4 + 3][nrow] = v.w;
        }
        __syncthreads();

        #pragma unroll
        for (int k = 0; k < GBK; k++) {
            float4 a0 = *reinterpret_cast<const float4*>(&As[k][ty * 8]);
            float4 a1 = *reinterpret_cast<const float4*>(&As[k][ty * 8 + 4]);
            float4 b0 = *reinterpret_cast<const float4*>(&Bs[k][tx * 8]);
            float4 b1 = *reinterpret_cast<const float4*>(&Bs[k][tx * 8 + 4]);
            float av[8] = {a0.x, a0.y, a0.z, a0.w, a1.x, a1.y, a1.z, a1.w};
            float bv[8] = {b0.x, b0.y, b0.z, b0.w, b1.x, b1.y, b1.z, b1.w};
            #pragma unroll
            for (int i = 0; i < 8; i++)
                #pragma unroll
                for (int j = 0; j < 8; j++)
                    acc[i][j] = fmaf(av[i], bv[j], acc[i][j]);
        }
        __syncthreads();
    }

    #pragma unroll
    for (int i = 0; i < 8; i++) {
        int t = bm * GBM + ty * 8 + i;
        float* outp = &g_gates[dir][t][rbase + tx * 8];
        float4 o0 = make_float4(acc[i][0] + bsum[0], acc[i][1] + bsum[1],
                                acc[i][2] + bsum[2], acc[i][3] + bsum[3]);
        float4 o1 = make_float4(acc[i][4] + bsum[4], acc[i][5] + bsum[5],
                                acc[i][6] + bsum[6], acc[i][7] + bsum[7]);
        *reinterpret_cast<float4*>(&outp[0]) = o0;
        *reinterpret_cast<float4*>(&outp[4]) = o1;
    }
}

// ============================================================================
// Kernel B: persistent recurrence.
//  - warp 15: sole counter poller (ld.acquire broadcast) -> syncthreads
//  - warps 0-5: stage h into shared
//  - all 16 warps: packed f32x2 matvec (36 FFMA2/thread)
//  - warp 14: gate prefetch into smem (hidden behind matvec)
//  - warp 0: fuse + warp-local publish (stcg x3 + red.release by lane 0)
// ============================================================================
__global__ __launch_bounds__(REC_THREADS, 1) void lstm_rec_kernel(
    const float* __restrict__ Whhf, const float* __restrict__ Whhb, int whh_cl,
    const float* __restrict__ Wt, int wt_cl,
    const float* __restrict__ bt, int bt_cl,
    float* __restrict__ out, int out_cl)
{
    __shared__ __align__(16) float sh[HID];
    __shared__ __align__(16) float sg[48];
    __shared__ __align__(16) float spg[48];
    __shared__ __align__(16) float hout[M_PER_CTA];

    const int tid  = threadIdx.x;
    const int b    = blockIdx.x;
    const int dir  = b >> 6;
    const int lb   = b & 63;
    const int m0   = lb * M_PER_CTA;

    const int w    = tid >> 5;
    const int l    = tid & 31;
    const int gate = w >> 2;          // 0..3
    const int rsub = 3 * (w & 3);     // 0,3,6,9

    const float* __restrict__ Whh = dir ? Whhb : Whhf;
    unsigned* ctr = &g_ctr[dir * 128];

    // register-resident W_hh slice, packed as f32x2 pairs: 3 rows x 12 pairs
    uint64_t wr2[3][12];
    #pragma unroll
    for (int j = 0; j < 3; j++) {
        int grow = gate * HID + m0 + rsub + j;
        #pragma unroll
        for (int c = 0; c < 6; c++) {
            size_t off = cmin((size_t)grow * HID + c * 128 + 4 * l,
                              (size_t)whh_cl);
            float4 v = *reinterpret_cast<const float4*>(&Whh[off]);
            wr2[j][2 * c + 0] = pack2(v.x, v.y);
            wr2[j][2 * c + 1] = pack2(v.z, v.w);
        }
    }

    float creg = 0.0f;                 // warp 0 lanes 0..11 only
    const float* Gd = &g_gates[dir][0][0];

    for (int t = 0; t < S_LEN; t++) {
        // gate prefetch (warp 14) — consumed after next-next barrier
        float pg0 = 0.f, pg1 = 0.f, pg2 = 0.f, pg3 = 0.f;
        if (w == 14 && l < M_PER_CTA) {
            const float* G = Gd + (size_t)t * HX4;
            int m = m0 + l;
            pg0 = __ldcg(&G[m]);
            pg1 = __ldcg(&G[768 + m]);
            pg2 = __ldcg(&G[1536 + m]);
            pg3 = __ldcg(&G[2304 + m]);
        }

        // single-warp poll (broadcast address)
        if (w == 15) {
            const unsigned target = 64u * (unsigned)t;
            while (ld_acq(ctr) < target) { }
        }
        __syncthreads();                        // propagates acquire to CTA

        // stage h (read buffer parity = t&1)
        if (tid < HID / 4) {
            float4 hv = __ldcg(reinterpret_cast<const float4*>(
                                   &g_h[t & 1][dir][tid * 4]));
            *reinterpret_cast<float4*>(&sh[tid * 4]) = hv;
        }
        __syncthreads();

        // packed matvec: 3 rows x 24 cols -> 36 FFMA2, 6 accumulators
        uint64_t a0 = 0, a1 = 0, a2 = 0, a3 = 0, a4 = 0, a5 = 0;
        #pragma unroll
        for (int c = 0; c < 6; c++) {
            float4 hv = *reinterpret_cast<const float4*>(&sh[c * 128 + 4 * l]);
            uint64_t h01 = pack2(hv.x, hv.y);
            uint64_t h23 = pack2(hv.z, hv.w);
            ffma2(a0, wr2[0][2 * c], h01); ffma2(a1, wr2[0][2 * c + 1], h23);
            ffma2(a2, wr2[1][2 * c], h01); ffma2(a3, wr2[1][2 * c + 1], h23);
            ffma2(a4, wr2[2][2 * c], h01); ffma2(a5, wr2[2][2 * c + 1], h23);
        }
        float2 f0 = unpack2(a0), f1 = unpack2(a1);
        float2 f2 = unpack2(a2), f3 = unpack2(a3);
        float2 f4 = unpack2(a4), f5 = unpack2(a5);
        float r0 = (f0.x + f0.y) + (f1.x + f1.y);
        float r1 = (f2.x + f2.y) + (f3.x + f3.y);
        float r2 = (f4.x + f4.y) + (f5.x + f5.y);
        #pragma unroll
        for (int off = 16; off; off >>= 1) {
            r0 += __shfl_xor_sync(0xffffffffu, r0, off);
            r1 += __shfl_xor_sync(0xffffffffu, r1, off);
            r2 += __shfl_xor_sync(0xffffffffu, r2, off);
        }
        if (l == 0) {
            sg[gate * 12 + rsub + 0] = r0;
            sg[gate * 12 + rsub + 1] = r1;
            sg[gate * 12 + rsub + 2] = r2;
        }
        if (w == 14 && l < M_PER_CTA) {     // park prefetched gates in smem
            spg[l] = pg0; spg[12 + l] = pg1; spg[24 + l] = pg2; spg[36 + l] = pg3;
        }
        __syncthreads();

        // fuse + publish (warp 0 only; other warps race ahead to next poll)
        if (w == 0) {
            if (l < M_PER_CTA) {
                float gi = sg[l]      + spg[l];
                float gf = sg[12 + l] + spg[12 + l];
                float gg = sg[24 + l] + spg[24 + l];
                float go = sg[36 + l] + spg[36 + l];
                float cn = sigmf(gf) * creg + sigmf(gi) * tanhf(gg);
                float hn = sigmf(go) * tanhf(cn);
                creg = cn;
                hout[l] = hn;
            }
            __syncwarp();
            if (l == 0) {
                float4* dst = reinterpret_cast<float4*>(
                    &g_h[(t & 1) ^ 1][dir][m0]);
                const float4* src = reinterpret_cast<const float4*>(hout);
                __stcg(&dst[0], src[0]);
                __stcg(&dst[1], src[1]);
                __stcg(&dst[2], src[2]);
                red_rel_add1(ctr);        // release by the storing thread
            }
        }
    }

    // -------- tail: block 0 computes hidden2tag once both dirs finish ------
    if (b == 0) {
        const unsigned done = 64u * (unsigned)S_LEN;
        while (ld_acq(&g_ctr[0])   < done) { }
        while (ld_acq(&g_ctr[128]) < done) { }
        const float* hf = g_h[0][0];       // S_LEN even -> final h in buffer 0
        const float* hb = g_h[0][1];
        for (int o = w; o < 20; o += 16) {
            float s = 0.0f;
            for (int i = 0; i < 48; i++) {
                int k = i * 32 + l;
                float x = (k < HID) ? __ldcg(&hf[k]) : __ldcg(&hb[k - HID]);
                int wk = o * (2 * HID) + k; if (wk > wt_cl) wk = wt_cl;
                s = fmaf(Wt[wk], x, s);
            }
            #pragma unroll
            for (int off = 16; off; off >>= 1)
                s += __shfl_xor_sync(0xffffffffu, s, off);
            if (l == 0 && o <= out_cl) {
                int bw = (o > bt_cl) ? bt_cl : o;
                out[o] = s + bt[bw];
            }
        }
    }
}

// ============================================================================
extern "C" void kernel_launch(void* const* d_in, const int* in_sizes, int n_in,
                              void* d_out, int out_size)
{
    // VERIFIED mapping (round-13 forensics): signature order, element counts:
    //  0 inpu(int64 x8192) 1 emb(100000x300) 2 W_ih_f(3072x300)
    //  3 W_hh_f(3072x768)  4 b_ih_f 5 b_hh_f 6 W_ih_b(3072x300)
    //  7 W_hh_b(3072x768)  8 b_ih_b 9 b_hh_b 10 W_tag(20x1536) 11 b_tag(20)
    const int*   inpu = (const int*)  d_in[0];
    const float* emb  = (const float*)d_in[1];
    const float* Wihf = (const float*)d_in[2];
    const float* Whhf = (const float*)d_in[3];
    const float* bihf = (const float*)d_in[4];
    const float* bhhf = (const float*)d_in[5];
    const float* Wihb = (const float*)d_in[6];
    const float* Whhb = (const float*)d_in[7];
    const float* bihb = (const float*)d_in[8];
    const float* bhhb = (const float*)d_in[9];
    const float* Wtag = (const float*)d_in[10];
    const float* btag = (const float*)d_in[11];
    float* out = (float*)d_out;

    auto c4 = [&](int i) -> int {
        long long s = in_sizes[i];
        long long c = (s / 4) * 4 - 4;
        if (c < 0) c = 0;
        return (int)c;
    };
    auto c1 = [&](int i) -> int {
        long long s = in_sizes[i];
        return (int)((s > 0) ? s - 1 : 0);
    };

    dim3 ggrid(S_LEN / GBM, (NDIR * HX4) / GBN);   // (64, 48)
    gates_gemm_kernel<<<ggrid, GEMM_THREADS>>>(
        inpu, c1(0), emb, c4(1), Wihf, Wihb, c4(2),
        bihf, bhhf, bihb, bhhb, c1(4));
    lstm_rec_kernel<<<NDIR * CTAS_PER_DIR, REC_THREADS>>>(
        Whhf, Whhb, c4(3), Wtag, c1(10), btag, c1(11), out,
        (out_size > 0) ? out_size - 1 : 0);
}